// round 6
// baseline (speedup 1.0000x reference)
#include <cuda_runtime.h>
#include <cuda_bf16.h>
#include <cuda_fp16.h>
#include <math_constants.h>

#define N_PTS 16384
#define C_DIM 64
#define K_NN 16
#define K_SCR 24
#define K_CAND 48        // 2 halves x 24

__device__ float g_norms[N_PTS];
__device__ __nv_bfloat16 g_xbf[N_PTS * C_DIM];
__device__ __half g_s[(size_t)N_PTS * N_PTS];     // 512 MB screen metrics
__device__ int g_pi[N_PTS * K_CAND];
__device__ int g_knn[N_PTS * K_NN];

// ---------------------------------------------------------------------------
// Kernel 0: norms + bf16 copy of x
// ---------------------------------------------------------------------------
__global__ __launch_bounds__(256) void prep_kernel(const float* __restrict__ x) {
    int i = blockIdx.x * 256 + threadIdx.x;
    const float4* xv = (const float4*)(x + (size_t)i * C_DIM);
    __nv_bfloat162* ob = (__nv_bfloat162*)(g_xbf + (size_t)i * C_DIM);
    float s = 0.f;
#pragma unroll
    for (int d = 0; d < 16; ++d) {
        float4 v = xv[d];
        s += v.x * v.x + v.y * v.y + v.z * v.z + v.w * v.w;
        ob[2 * d]     = __floats2bfloat162_rn(v.x, v.y);
        ob[2 * d + 1] = __floats2bfloat162_rn(v.z, v.w);
    }
    g_norms[i] = s;
}

// ---------------------------------------------------------------------------
// Kernel 1: bf16 HMMA GEMM -> fp16 screen metric  m[q][c] = nc - 2*dot(q,c)
// CTA = 128x128 tile, 8 warps (warp = 16 rows x 128 cols), K=64 in one shot.
// ---------------------------------------------------------------------------
#define LDA 72     // padded halves per row (conflict-free frag LDS)
#define LDSG 136   // stage pad

__device__ __forceinline__ void mma_bf16(float* c, const unsigned* a, const unsigned* b) {
    asm volatile(
        "mma.sync.aligned.m16n8k16.row.col.f32.bf16.bf16.f32 "
        "{%0,%1,%2,%3}, {%4,%5,%6,%7}, {%8,%9}, {%0,%1,%2,%3};\n"
        : "+f"(c[0]), "+f"(c[1]), "+f"(c[2]), "+f"(c[3])
        : "r"(a[0]), "r"(a[1]), "r"(a[2]), "r"(a[3]), "r"(b[0]), "r"(b[1]));
}

#define GEMM_SMEM (2 * 128 * LDA * 2 + 512)   // A + B (stage aliases A/B) + norms

__global__ __launch_bounds__(256) void gemm_kernel() {
    extern __shared__ char smem[];
    __nv_bfloat16* sA = (__nv_bfloat16*)smem;
    __nv_bfloat16* sB = sA + 128 * LDA;
    float* sn = (float*)(smem + 2 * 128 * LDA * 2);

    int tid = threadIdx.x;
    int lane = tid & 31, w = tid >> 5;
    int Q0 = blockIdx.x * 128, C0 = blockIdx.y * 128;

    for (int u = tid; u < 1024; u += 256) {          // 128 rows x 8 16B-chunks
        int r = u >> 3, ch = u & 7;
        *(uint4*)(sA + r * LDA + ch * 8) = *(const uint4*)(g_xbf + (size_t)(Q0 + r) * 64 + ch * 8);
        *(uint4*)(sB + r * LDA + ch * 8) = *(const uint4*)(g_xbf + (size_t)(C0 + r) * 64 + ch * 8);
    }
    if (tid < 128) sn[tid] = g_norms[C0 + tid];
    __syncthreads();

    int g = lane >> 2, t4 = lane & 3;
    int rA = w * 16;
    float acc[16][4];
#pragma unroll
    for (int nf = 0; nf < 16; ++nf)
#pragma unroll
        for (int e = 0; e < 4; ++e) acc[nf][e] = 0.f;

#pragma unroll
    for (int ks = 0; ks < 4; ++ks) {
        int k0 = ks * 16;
        unsigned a[4];
        const __nv_bfloat16* pa = sA + (rA + g) * LDA + k0 + t4 * 2;
        a[0] = *(const unsigned*)pa;
        a[1] = *(const unsigned*)(pa + 8 * LDA);
        a[2] = *(const unsigned*)(pa + 8);
        a[3] = *(const unsigned*)(pa + 8 * LDA + 8);
#pragma unroll
        for (int nf = 0; nf < 16; ++nf) {
            const __nv_bfloat16* pb = sB + (nf * 8 + g) * LDA + k0 + t4 * 2;
            unsigned b[2];
            b[0] = *(const unsigned*)pb;
            b[1] = *(const unsigned*)(pb + 8);
            mma_bf16(acc[nf], a, b);
        }
    }
    __syncthreads();                    // done with sA/sB -> reuse as fp16 stage

    __half* stage = (__half*)smem;      // 128 x LDSG halves = 34.8 KB (fits in A+B)
#pragma unroll
    for (int nf = 0; nf < 16; ++nf) {
        int col = nf * 8 + t4 * 2;
        float n0 = sn[col], n1 = sn[col + 1];
        __half2 h01 = __floats2half2_rn(n0 - 2.f * acc[nf][0], n1 - 2.f * acc[nf][1]);
        __half2 h23 = __floats2half2_rn(n0 - 2.f * acc[nf][2], n1 - 2.f * acc[nf][3]);
        *(__half2*)(stage + (rA + g) * LDSG + col)     = h01;
        *(__half2*)(stage + (rA + g + 8) * LDSG + col) = h23;
    }
    __syncthreads();

    for (int u = tid; u < 2048; u += 256) {          // coalesced 16B stores
        int r = u >> 4, seg = u & 15;
        uint4 v = *(const uint4*)(stage + r * LDSG + seg * 8);
        *(uint4*)(g_s + (size_t)(Q0 + r) * N_PTS + C0 + seg * 8) = v;
    }
}

// ---------------------------------------------------------------------------
// Kernel 2: screen. 2 threads per query, each scans 8192 fp16 metrics with a
// 4-deep cp.async ring, keeps top-24 (exact-index, self excluded).
// ---------------------------------------------------------------------------
#define SCR_SMEM (4 * 4 * 256 * 16)   // 4 stages x 4 chunks x 256 thr x 16B

__device__ __forceinline__ void cp16(void* dst, const void* src) {
    unsigned d = (unsigned)__cvta_generic_to_shared(dst);
    asm volatile("cp.async.cg.shared.global [%0], [%1], 16;\n" :: "r"(d), "l"(src));
}

__global__ __launch_bounds__(256) void screen_kernel() {
    extern __shared__ char smem[];
    uint4* ring = (uint4*)smem;        // [stage][chunk][tid]

    int tid = threadIdx.x;
    int gt = blockIdx.x * 256 + tid;
    int q = gt >> 1, half = gt & 1;

    const uint4* row = (const uint4*)(g_s + (size_t)q * N_PTS + half * 8192); // 1024 uint4

    float bd[K_SCR];
    int   bi[K_SCR];
#pragma unroll
    for (int s = 0; s < K_SCR; ++s) { bd[s] = CUDART_INF_F; bi[s] = 0; }

    // prologue: stage batches 0..3
#pragma unroll
    for (int st = 0; st < 4; ++st) {
#pragma unroll
        for (int j = 0; j < 4; ++j)
            cp16(&ring[(st * 4 + j) * 256 + tid], &row[st * 4 + j]);
        asm volatile("cp.async.commit_group;\n");
    }

    int cbase = half * 8192;
    for (int bt = 0; bt < 256; ++bt) {
        asm volatile("cp.async.wait_group %0;\n" :: "n"(3));
        int st = bt & 3;
        uint4 v[4];
#pragma unroll
        for (int j = 0; j < 4; ++j) v[j] = ring[(st * 4 + j) * 256 + tid];

        // issue batch bt+4, always commit to keep group accounting aligned
        if (bt + 4 < 256) {
#pragma unroll
            for (int j = 0; j < 4; ++j)
                cp16(&ring[(st * 4 + j) * 256 + tid], &row[(bt + 4) * 4 + j]);
        }
        asm volatile("cp.async.commit_group;\n");

#pragma unroll
        for (int j = 0; j < 4; ++j) {
            const __half2* h = (const __half2*)&v[j];
#pragma unroll
            for (int p = 0; p < 4; ++p) {
                float2 f = __half22float2(h[p]);
                int c0 = cbase + bt * 32 + j * 8 + p * 2;
#pragma unroll
                for (int e = 0; e < 2; ++e) {
                    float m = (e == 0) ? f.x : f.y;
                    int c = c0 + e;
                    if (m < bd[K_SCR - 1] && c != q) {
                        float cd = m; int ci = c;
#pragma unroll
                        for (int s = 0; s < K_SCR; ++s) {
                            if (cd < bd[s]) {
                                float td = bd[s]; bd[s] = cd; cd = td;
                                int   ti = bi[s]; bi[s] = ci; ci = ti;
                            }
                        }
                    }
                }
            }
        }
    }
#pragma unroll
    for (int s = 0; s < K_SCR; ++s)
        g_pi[q * K_CAND + half * K_SCR + s] = bi[s];
}

// ---------------------------------------------------------------------------
// Kernel 3: exact fp32 rerank of 48 screened candidates -> top-16 set
// ---------------------------------------------------------------------------
__global__ __launch_bounds__(256) void rerank_kernel(const float* __restrict__ x) {
    __shared__ float sd[8][K_CAND];
    __shared__ int   si[8][K_CAND];
    int w = threadIdx.x >> 5, lane = threadIdx.x & 31;
    int q = blockIdx.x * 8 + w;
    const float4* xq = (const float4*)(x + (size_t)q * C_DIM);
    float nq = g_norms[q];

#pragma unroll
    for (int rep = 0; rep < 2; ++rep) {
        int i = rep * 32 + lane;
        if (i < K_CAND) {
            int c = g_pi[q * K_CAND + i];
            const float4* xc = (const float4*)(x + (size_t)c * C_DIM);
            float a0 = 0.f, a1 = 0.f, a2 = 0.f, a3 = 0.f;
#pragma unroll
            for (int d = 0; d < 16; ++d) {
                float4 u = xq[d];
                float4 v = xc[d];
                a0 = fmaf(u.x, v.x, a0);
                a1 = fmaf(u.y, v.y, a1);
                a2 = fmaf(u.z, v.z, a2);
                a3 = fmaf(u.w, v.w, a3);
            }
            float dot = (a0 + a1) + (a2 + a3);
            sd[w][i] = nq + g_norms[c] - 2.f * dot;
            si[w][i] = c;
        }
    }
    __syncwarp();
    if (lane == 0) {
#pragma unroll 1
        for (int s = 0; s < K_NN; ++s) {
            float best = CUDART_INF_F; int bj = 0;
#pragma unroll 1
            for (int j = 0; j < K_CAND; ++j)
                if (sd[w][j] < best) { best = sd[w][j]; bj = j; }
            g_knn[q * K_NN + s] = si[w][bj];
            sd[w][bj] = CUDART_INF_F;
        }
    }
}

// ---------------------------------------------------------------------------
// Kernel 4: gather + edge-MLP + relu + max over K + pixel-shuffle (R5 version)
// ---------------------------------------------------------------------------
#define MLP_SMEM_FLOATS (32768 + 8 * 2048)

__global__ __launch_bounds__(256) void mlp_kernel(const float* __restrict__ x,
                                                  const float* __restrict__ W,
                                                  const float* __restrict__ b,
                                                  float* __restrict__ y) {
    extern __shared__ float fsm[];
    float* sW    = fsm;
    float* sfeat = fsm + 32768;

    int tid  = threadIdx.x;
    int warp = tid >> 5;
    int lane = tid & 31;

    {
        const float4* Wv = (const float4*)W;
        float4* sWv = (float4*)sW;
        for (int i = tid; i < 8192; i += 256) sWv[i] = Wv[i];
    }
    float bb[8];
#pragma unroll
    for (int k = 0; k < 8; ++k) bb[k] = b[lane * 8 + k];
    __syncthreads();

    float* f = sfeat + warp * 2048;
    const float4* f4  = (const float4*)f;
    const float4* sW4 = (const float4*)sW;

    for (int qg = blockIdx.x; qg < N_PTS / 8; qg += gridDim.x) {
        int q = qg * 8 + warp;

        float xi0 = x[(size_t)q * 64 + lane];
        float xi1 = x[(size_t)q * 64 + 32 + lane];
#pragma unroll 1
        for (int n = 0; n < 16; ++n) {
            int j = g_knn[q * 16 + n];
            float v0 = x[(size_t)j * 64 + lane];
            float v1 = x[(size_t)j * 64 + 32 + lane];
            f[n * 128 + lane]      = xi0;
            f[n * 128 + 32 + lane] = xi1;
            f[n * 128 + 64 + lane] = v0 - xi0;
            f[n * 128 + 96 + lane] = v1 - xi1;
        }
        __syncwarp();

        float vmax[8];
#pragma unroll
        for (int k = 0; k < 8; ++k) vmax[k] = 0.f;

#pragma unroll 1
        for (int ch = 0; ch < 2; ++ch) {
            float acc[8][8];
#pragma unroll
            for (int n = 0; n < 8; ++n)
#pragma unroll
                for (int k = 0; k < 8; ++k) acc[n][k] = bb[k];

#pragma unroll 1
            for (int d = 0; d < 128; d += 4) {
                float4 fv[8];
#pragma unroll
                for (int n = 0; n < 8; ++n)
                    fv[n] = f4[(ch * 8 + n) * 32 + (d >> 2)];
#pragma unroll
                for (int dd = 0; dd < 4; ++dd) {
                    float4 w0 = sW4[(d + dd) * 64 + lane * 2];
                    float4 w1 = sW4[(d + dd) * 64 + lane * 2 + 1];
#pragma unroll
                    for (int n = 0; n < 8; ++n) {
                        float fe = (dd == 0) ? fv[n].x : (dd == 1) ? fv[n].y
                                 : (dd == 2) ? fv[n].z : fv[n].w;
                        acc[n][0] = fmaf(fe, w0.x, acc[n][0]);
                        acc[n][1] = fmaf(fe, w0.y, acc[n][1]);
                        acc[n][2] = fmaf(fe, w0.z, acc[n][2]);
                        acc[n][3] = fmaf(fe, w0.w, acc[n][3]);
                        acc[n][4] = fmaf(fe, w1.x, acc[n][4]);
                        acc[n][5] = fmaf(fe, w1.y, acc[n][5]);
                        acc[n][6] = fmaf(fe, w1.z, acc[n][6]);
                        acc[n][7] = fmaf(fe, w1.w, acc[n][7]);
                    }
                }
            }
#pragma unroll
            for (int n = 0; n < 8; ++n)
#pragma unroll
                for (int k = 0; k < 8; ++k)
                    vmax[k] = fmaxf(vmax[k], fmaxf(acc[n][k], 0.f));
        }

#pragma unroll
        for (int r = 0; r < 4; ++r) {
            float2 v = make_float2(vmax[r], vmax[4 + r]);
            ((float2*)(y + (size_t)(q * 4 + r) * 64))[lane] = v;
        }
        __syncwarp();
    }
}

// ---------------------------------------------------------------------------
extern "C" void kernel_launch(void* const* d_in, const int* in_sizes, int n_in,
                              void* d_out, int out_size) {
    const float* x = (const float*)d_in[0];
    const float* W = (const float*)d_in[1];
    const float* b = (const float*)d_in[2];
    float* y = (float*)d_out;

    prep_kernel<<<N_PTS / 256, 256>>>(x);

    dim3 ggrid(N_PTS / 128, N_PTS / 128);
    gemm_kernel<<<ggrid, 256, GEMM_SMEM>>>();

    cudaFuncSetAttribute(screen_kernel,
                         cudaFuncAttributeMaxDynamicSharedMemorySize, SCR_SMEM);
    screen_kernel<<<N_PTS * 2 / 256, 256, SCR_SMEM>>>();

    rerank_kernel<<<N_PTS / 8, 256>>>(x);

    cudaFuncSetAttribute(mlp_kernel,
                         cudaFuncAttributeMaxDynamicSharedMemorySize,
                         MLP_SMEM_FLOATS * sizeof(float));
    mlp_kernel<<<148, 256, MLP_SMEM_FLOATS * sizeof(float)>>>(x, W, b, y);
}

// round 7
// speedup vs baseline: 2.4416x; 2.4416x over previous
#include <cuda_runtime.h>
#include <cuda_bf16.h>
#include <math_constants.h>

#define N_PTS 16384
#define C_DIM 64
#define K_NN 16
#define SPLIT 2
#define SEG (N_PTS / SPLIT)
#define TILE 128
#define NTILE (SEG / TILE)
#define K_SEL 20
#define K_CAND 80          // 4 lists x 20

__device__ float g_norms[N_PTS];
__device__ __nv_bfloat16 g_xbf[N_PTS * C_DIM];
__device__ int g_pi[N_PTS * K_CAND];
__device__ int g_knn[N_PTS * K_NN];

// ---------------------------------------------------------------------------
// Kernel 0: norms + bf16 copy of x
// ---------------------------------------------------------------------------
__global__ __launch_bounds__(256) void prep_kernel(const float* __restrict__ x) {
    int i = blockIdx.x * 256 + threadIdx.x;
    const float4* xv = (const float4*)(x + (size_t)i * C_DIM);
    __nv_bfloat162* ob = (__nv_bfloat162*)(g_xbf + (size_t)i * C_DIM);
    float s = 0.f;
#pragma unroll
    for (int d = 0; d < 16; ++d) {
        float4 v = xv[d];
        s += v.x * v.x + v.y * v.y + v.z * v.z + v.w * v.w;
        ob[2 * d]     = __floats2bfloat162_rn(v.x, v.y);
        ob[2 * d + 1] = __floats2bfloat162_rn(v.z, v.w);
    }
    g_norms[i] = s;
}

// ---------------------------------------------------------------------------
// Kernel 1: fused HMMA distance tile (smem-resident) + top-20 screen.
// grid (128, SPLIT). CTA: 128 queries x 8192 candidates in 64 tiles of 128.
// Layout validated in R6 (rel_err 0.0 on the same mma path).
// ---------------------------------------------------------------------------
#define LDA 72      // bf16 per row, padded
#define LDD 132     // floats per d2 row, padded

#define KNN_SMEM (2 * 128 * LDA * 2 + 512 + 128 * LDD * 4)   // 104960 B

__device__ __forceinline__ void mma_bf16(float* c, const unsigned* a, const unsigned* b) {
    asm volatile(
        "mma.sync.aligned.m16n8k16.row.col.f32.bf16.bf16.f32 "
        "{%0,%1,%2,%3}, {%4,%5,%6,%7}, {%8,%9}, {%0,%1,%2,%3};\n"
        : "+f"(c[0]), "+f"(c[1]), "+f"(c[2]), "+f"(c[3])
        : "r"(a[0]), "r"(a[1]), "r"(a[2]), "r"(a[3]), "r"(b[0]), "r"(b[1]));
}

__global__ __launch_bounds__(256) void knn_kernel() {
    extern __shared__ char smem[];
    __nv_bfloat16* sA = (__nv_bfloat16*)smem;                 // 128 x LDA
    __nv_bfloat16* sB = sA + 128 * LDA;                       // 128 x LDA
    float* snc = (float*)(smem + 2 * 128 * LDA * 2);          // 128
    float* d2  = snc + 128;                                   // 128 x LDD

    int tid = threadIdx.x;
    int lane = tid & 31, w = tid >> 5;
    int Q0 = blockIdx.x * 128;
    int s0 = blockIdx.y;

    // Q tile -> smem (persistent)
    for (int u = tid; u < 1024; u += 256) {
        int r = u >> 3, ch = u & 7;
        *(uint4*)(sA + r * LDA + ch * 8) =
            *(const uint4*)(g_xbf + (size_t)(Q0 + r) * 64 + ch * 8);
    }
    __syncthreads();

    // preload A fragments (loop-invariant): warp w covers rows w*16..w*16+15
    int g = lane >> 2, t4 = lane & 3;
    unsigned afr[4][4];
    {
        const __nv_bfloat16* pa0 = sA + (w * 16 + g) * LDA + t4 * 2;
#pragma unroll
        for (int ks = 0; ks < 4; ++ks) {
            const __nv_bfloat16* pa = pa0 + ks * 16;
            afr[ks][0] = *(const unsigned*)pa;
            afr[ks][1] = *(const unsigned*)(pa + 8 * LDA);
            afr[ks][2] = *(const unsigned*)(pa + 8);
            afr[ks][3] = *(const unsigned*)(pa + 8 * LDA + 8);
        }
    }

    // selection state: thread handles query row (tid&127), col-half (tid>>7)
    int qrow = tid & 127, half = tid >> 7;
    int myq = Q0 + qrow;
    float bd[K_SEL];
    int   bi[K_SEL];
#pragma unroll
    for (int s = 0; s < K_SEL; ++s) { bd[s] = CUDART_INF_F; bi[s] = 0; }

    for (int tile = 0; tile < NTILE; ++tile) {
        int Cb = s0 * SEG + tile * TILE;
        __syncthreads();                       // prev scan done before B/d2 reuse
        for (int u = tid; u < 1024; u += 256) {
            int r = u >> 3, ch = u & 7;
            *(uint4*)(sB + r * LDA + ch * 8) =
                *(const uint4*)(g_xbf + (size_t)(Cb + r) * 64 + ch * 8);
        }
        if (tid < 128) snc[tid] = g_norms[Cb + tid];
        __syncthreads();

        // MMA: 16 col-blocks of 8; m = nc - 2*dot into d2
#pragma unroll
        for (int nf = 0; nf < 16; ++nf) {
            float acc[4] = {0.f, 0.f, 0.f, 0.f};
            const __nv_bfloat16* pb0 = sB + (nf * 8 + g) * LDA + t4 * 2;
#pragma unroll
            for (int ks = 0; ks < 4; ++ks) {
                unsigned b[2];
                b[0] = *(const unsigned*)(pb0 + ks * 16);
                b[1] = *(const unsigned*)(pb0 + ks * 16 + 8);
                mma_bf16(acc, afr[ks], b);
            }
            int col = nf * 8 + t4 * 2;
            float n0 = snc[col], n1 = snc[col + 1];
            *(float2*)&d2[(w * 16 + g) * LDD + col] =
                make_float2(fmaf(-2.f, acc[0], n0), fmaf(-2.f, acc[1], n1));
            *(float2*)&d2[(w * 16 + g + 8) * LDD + col] =
                make_float2(fmaf(-2.f, acc[2], n0), fmaf(-2.f, acc[3], n1));
        }
        __syncthreads();

        // scan this tile: 64 cols per thread
        const float* drow = d2 + qrow * LDD + half * 64;
        int cbase = Cb + half * 64;
#pragma unroll 4
        for (int j4 = 0; j4 < 16; ++j4) {
            float4 v = *(const float4*)(drow + j4 * 4);
#pragma unroll
            for (int e = 0; e < 4; ++e) {
                float m = (e == 0) ? v.x : (e == 1) ? v.y : (e == 2) ? v.z : v.w;
                int c = cbase + j4 * 4 + e;
                if (m < bd[K_SEL - 1] && c != myq) {
                    float cd = m; int ci = c;
#pragma unroll
                    for (int s = 0; s < K_SEL; ++s) {
                        if (cd < bd[s]) {
                            float td = bd[s]; bd[s] = cd; cd = td;
                            int   ti = bi[s]; bi[s] = ci; ci = ti;
                        }
                    }
                }
            }
        }
    }

    int lbase = myq * K_CAND + (s0 * 2 + half) * K_SEL;
#pragma unroll
    for (int s = 0; s < K_SEL; ++s) g_pi[lbase + s] = bi[s];
}

// ---------------------------------------------------------------------------
// Kernel 2: exact fp32 rerank of 80 candidates -> top-16 set (warp/query).
// Butterfly-shuffle argmin, fully warp-parallel (fixes R6's serial loop).
// ---------------------------------------------------------------------------
__global__ __launch_bounds__(256) void rerank_kernel(const float* __restrict__ x) {
    int w = threadIdx.x >> 5, lane = threadIdx.x & 31;
    int q = blockIdx.x * 8 + w;
    const float4* xq = (const float4*)(x + (size_t)q * C_DIM);

    float dv[3]; int ci[3];
#pragma unroll
    for (int s = 0; s < 3; ++s) {
        int i = lane + s * 32;
        if (i < K_CAND) {
            int c = g_pi[q * K_CAND + i];
            const float4* xc = (const float4*)(x + (size_t)c * C_DIM);
            float a0 = 0.f, a1 = 0.f, a2 = 0.f, a3 = 0.f;
#pragma unroll
            for (int d = 0; d < 16; ++d) {
                float4 u = xq[d], v = xc[d];
                a0 = fmaf(u.x, v.x, a0);
                a1 = fmaf(u.y, v.y, a1);
                a2 = fmaf(u.z, v.z, a2);
                a3 = fmaf(u.w, v.w, a3);
            }
            float dot = (a0 + a1) + (a2 + a3);
            dv[s] = g_norms[c] - 2.f * dot;     // nq constant per q: rank-safe
            ci[s] = c;
        } else { dv[s] = CUDART_INF_F; ci[s] = -1; }
    }

#pragma unroll 1
    for (int s = 0; s < K_NN; ++s) {
        float m = dv[0]; int idx = ci[0], key = lane * 4;
        if (dv[1] < m) { m = dv[1]; idx = ci[1]; key = lane * 4 + 1; }
        if (dv[2] < m) { m = dv[2]; idx = ci[2]; key = lane * 4 + 2; }
#pragma unroll
        for (int off = 16; off > 0; off >>= 1) {
            float om = __shfl_xor_sync(0xffffffffu, m, off);
            int   oi = __shfl_xor_sync(0xffffffffu, idx, off);
            int   ok = __shfl_xor_sync(0xffffffffu, key, off);
            if (om < m || (om == m && ok < key)) { m = om; idx = oi; key = ok; }
        }
        if ((key >> 2) == lane) dv[key & 3] = CUDART_INF_F;   // consume winner
        if (lane == 0) g_knn[q * K_NN + s] = idx;
    }
}

// ---------------------------------------------------------------------------
// Kernel 3: gather + edge-MLP + relu + max over K + pixel-shuffle (R5 version)
// ---------------------------------------------------------------------------
#define MLP_SMEM_FLOATS (32768 + 8 * 2048)

__global__ __launch_bounds__(256) void mlp_kernel(const float* __restrict__ x,
                                                  const float* __restrict__ W,
                                                  const float* __restrict__ b,
                                                  float* __restrict__ y) {
    extern __shared__ float fsm[];
    float* sW    = fsm;
    float* sfeat = fsm + 32768;

    int tid  = threadIdx.x;
    int warp = tid >> 5;
    int lane = tid & 31;

    {
        const float4* Wv = (const float4*)W;
        float4* sWv = (float4*)sW;
        for (int i = tid; i < 8192; i += 256) sWv[i] = Wv[i];
    }
    float bb[8];
#pragma unroll
    for (int k = 0; k < 8; ++k) bb[k] = b[lane * 8 + k];
    __syncthreads();

    float* f = sfeat + warp * 2048;
    const float4* f4  = (const float4*)f;
    const float4* sW4 = (const float4*)sW;

    for (int qg = blockIdx.x; qg < N_PTS / 8; qg += gridDim.x) {
        int q = qg * 8 + warp;

        float xi0 = x[(size_t)q * 64 + lane];
        float xi1 = x[(size_t)q * 64 + 32 + lane];
#pragma unroll 1
        for (int n = 0; n < 16; ++n) {
            int j = g_knn[q * 16 + n];
            float v0 = x[(size_t)j * 64 + lane];
            float v1 = x[(size_t)j * 64 + 32 + lane];
            f[n * 128 + lane]      = xi0;
            f[n * 128 + 32 + lane] = xi1;
            f[n * 128 + 64 + lane] = v0 - xi0;
            f[n * 128 + 96 + lane] = v1 - xi1;
        }
        __syncwarp();

        float vmax[8];
#pragma unroll
        for (int k = 0; k < 8; ++k) vmax[k] = 0.f;

#pragma unroll 1
        for (int ch = 0; ch < 2; ++ch) {
            float acc[8][8];
#pragma unroll
            for (int n = 0; n < 8; ++n)
#pragma unroll
                for (int k = 0; k < 8; ++k) acc[n][k] = bb[k];

#pragma unroll 1
            for (int d = 0; d < 128; d += 4) {
                float4 fv[8];
#pragma unroll
                for (int n = 0; n < 8; ++n)
                    fv[n] = f4[(ch * 8 + n) * 32 + (d >> 2)];
#pragma unroll
                for (int dd = 0; dd < 4; ++dd) {
                    float4 w0 = sW4[(d + dd) * 64 + lane * 2];
                    float4 w1 = sW4[(d + dd) * 64 + lane * 2 + 1];
#pragma unroll
                    for (int n = 0; n < 8; ++n) {
                        float fe = (dd == 0) ? fv[n].x : (dd == 1) ? fv[n].y
                                 : (dd == 2) ? fv[n].z : fv[n].w;
                        acc[n][0] = fmaf(fe, w0.x, acc[n][0]);
                        acc[n][1] = fmaf(fe, w0.y, acc[n][1]);
                        acc[n][2] = fmaf(fe, w0.z, acc[n][2]);
                        acc[n][3] = fmaf(fe, w0.w, acc[n][3]);
                        acc[n][4] = fmaf(fe, w1.x, acc[n][4]);
                        acc[n][5] = fmaf(fe, w1.y, acc[n][5]);
                        acc[n][6] = fmaf(fe, w1.z, acc[n][6]);
                        acc[n][7] = fmaf(fe, w1.w, acc[n][7]);
                    }
                }
            }
#pragma unroll
            for (int n = 0; n < 8; ++n)
#pragma unroll
                for (int k = 0; k < 8; ++k)
                    vmax[k] = fmaxf(vmax[k], fmaxf(acc[n][k], 0.f));
        }

#pragma unroll
        for (int r = 0; r < 4; ++r) {
            float2 v = make_float2(vmax[r], vmax[4 + r]);
            ((float2*)(y + (size_t)(q * 4 + r) * 64))[lane] = v;
        }
        __syncwarp();
    }
}

// ---------------------------------------------------------------------------
extern "C" void kernel_launch(void* const* d_in, const int* in_sizes, int n_in,
                              void* d_out, int out_size) {
    const float* x = (const float*)d_in[0];
    const float* W = (const float*)d_in[1];
    const float* b = (const float*)d_in[2];
    float* y = (float*)d_out;

    prep_kernel<<<N_PTS / 256, 256>>>(x);

    cudaFuncSetAttribute(knn_kernel,
                         cudaFuncAttributeMaxDynamicSharedMemorySize, KNN_SMEM);
    dim3 kgrid(N_PTS / 128, SPLIT);
    knn_kernel<<<kgrid, 256, KNN_SMEM>>>();

    rerank_kernel<<<N_PTS / 8, 256>>>(x);

    cudaFuncSetAttribute(mlp_kernel,
                         cudaFuncAttributeMaxDynamicSharedMemorySize,
                         MLP_SMEM_FLOATS * sizeof(float));
    mlp_kernel<<<148, 256, MLP_SMEM_FLOATS * sizeof(float)>>>(x, W, b, y);
}

// round 9
// speedup vs baseline: 2.6852x; 1.0998x over previous
#include <cuda_runtime.h>
#include <cuda_bf16.h>
#include <math_constants.h>
#include <cstdint>

#define N_PTS 16384
#define C_DIM 64
#define K_NN 16
#define SPLIT 4
#define SEG (N_PTS / SPLIT)
#define K_SEL 20
#define K_CAND 80        // SPLIT x K_SEL

__device__ float g_norms[N_PTS];
__device__ __nv_bfloat16 g_xbf[N_PTS * C_DIM];
__device__ int g_pi[N_PTS * K_CAND];
__device__ int g_knn[N_PTS * K_NN];

// ---------------------------------------------------------------------------
// Kernel 0: norms + bf16 copy of x
// ---------------------------------------------------------------------------
__global__ __launch_bounds__(256) void prep_kernel(const float* __restrict__ x) {
    int i = blockIdx.x * 256 + threadIdx.x;
    const float4* xv = (const float4*)(x + (size_t)i * C_DIM);
    __nv_bfloat162* ob = (__nv_bfloat162*)(g_xbf + (size_t)i * C_DIM);
    float s = 0.f;
#pragma unroll
    for (int d = 0; d < 16; ++d) {
        float4 v = xv[d];
        s += v.x * v.x + v.y * v.y + v.z * v.z + v.w * v.w;
        ob[2 * d]     = __floats2bfloat162_rn(v.x, v.y);
        ob[2 * d + 1] = __floats2bfloat162_rn(v.z, v.w);
    }
    g_norms[i] = s;
}

// ---------------------------------------------------------------------------
// Kernel 1: bf16x2 HFMA2 screen. 1 thread/query, top-20 per split.
// grid (128, SPLIT) = 512 CTAs x 128 thr; smem 16.5 KB -> all co-resident.
// Screen metric m = nc - 2*dot_bf16 (nq dropped: constant per query row).
// ---------------------------------------------------------------------------
#define QT 128
#define JT 128

__global__ __launch_bounds__(128) void screen_kernel() {
    __shared__ __nv_bfloat16 sc[JT * C_DIM];   // 16 KB candidate tile
    __shared__ float sn[JT];

    int t = threadIdx.x;
    int q = blockIdx.x * QT + t;
    int s0 = blockIdx.y;

    // query vector as 32 bf16x2 registers
    __nv_bfloat162 xq[32];
    {
        const uint4* xv = (const uint4*)(g_xbf + (size_t)q * C_DIM);
#pragma unroll
        for (int d = 0; d < 8; ++d) *(uint4*)&xq[4 * d] = xv[d];
    }

    float bd[K_SEL];
    int   bi[K_SEL];
#pragma unroll
    for (int s = 0; s < K_SEL; ++s) { bd[s] = CUDART_INF_F; bi[s] = 0; }

    int jbeg = s0 * SEG, jend = jbeg + SEG;
    for (int jt = jbeg; jt < jend; jt += JT) {
        __syncthreads();
        // linear coalesced copy: 1024 x 16B, conflict-free STS
        const uint4* src = (const uint4*)(g_xbf + (size_t)jt * C_DIM);
        uint4* dst = (uint4*)sc;
#pragma unroll
        for (int i = 0; i < 8; ++i) dst[t + i * 128] = src[t + i * 128];
        sn[t] = g_norms[jt + t];
        __syncthreads();

#pragma unroll 1
        for (int j = 0; j < JT; ++j) {
            const __nv_bfloat162* c = (const __nv_bfloat162*)(sc + j * C_DIM);
            __nv_bfloat162 a0 = __floats2bfloat162_rn(0.f, 0.f);
            __nv_bfloat162 a1 = a0, a2 = a0, a3 = a0;
#pragma unroll
            for (int d = 0; d < 8; ++d) {
                uint4 cv = ((const uint4*)c)[d];          // 4 bf16x2, broadcast
                const __nv_bfloat162* cc = (const __nv_bfloat162*)&cv;
                a0 = __hfma2(xq[4 * d],     cc[0], a0);
                a1 = __hfma2(xq[4 * d + 1], cc[1], a1);
                a2 = __hfma2(xq[4 * d + 2], cc[2], a2);
                a3 = __hfma2(xq[4 * d + 3], cc[3], a3);
            }
            float2 f0 = __bfloat1622float2(a0);
            float2 f1 = __bfloat1622float2(a1);
            float2 f2 = __bfloat1622float2(a2);
            float2 f3 = __bfloat1622float2(a3);
            float dot = ((f0.x + f0.y) + (f1.x + f1.y)) +
                        ((f2.x + f2.y) + (f3.x + f3.y));
            float m = fmaf(-2.f, dot, sn[j]);
            int c_idx = jt + j;
            if (m < bd[K_SEL - 1] && c_idx != q) {
                float cd = m; int ci = c_idx;
#pragma unroll
                for (int s = 0; s < K_SEL; ++s) {
                    if (cd < bd[s]) {
                        float td = bd[s]; bd[s] = cd; cd = td;
                        int   ti = bi[s]; bi[s] = ci; ci = ti;
                    }
                }
            }
        }
    }

    int lb = q * K_CAND + s0 * K_SEL;
#pragma unroll
    for (int s = 0; s < K_SEL; ++s) g_pi[lb + s] = bi[s];
}

// ---------------------------------------------------------------------------
// Kernel 2: exact fp32 rerank of 80 candidates -> top-16 set (warp/query).
// Butterfly-shuffle argmin, fully warp-parallel.
// ---------------------------------------------------------------------------
__global__ __launch_bounds__(256) void rerank_kernel(const float* __restrict__ x) {
    int w = threadIdx.x >> 5, lane = threadIdx.x & 31;
    int q = blockIdx.x * 8 + w;
    const float4* xq = (const float4*)(x + (size_t)q * C_DIM);

    float dv[3]; int ci[3];
#pragma unroll
    for (int s = 0; s < 3; ++s) {
        int i = lane + s * 32;
        if (i < K_CAND) {
            int c = g_pi[q * K_CAND + i];
            const float4* xc = (const float4*)(x + (size_t)c * C_DIM);
            float a0 = 0.f, a1 = 0.f, a2 = 0.f, a3 = 0.f;
#pragma unroll
            for (int d = 0; d < 16; ++d) {
                float4 u = xq[d], v = xc[d];
                a0 = fmaf(u.x, v.x, a0);
                a1 = fmaf(u.y, v.y, a1);
                a2 = fmaf(u.z, v.z, a2);
                a3 = fmaf(u.w, v.w, a3);
            }
            float dot = (a0 + a1) + (a2 + a3);
            dv[s] = g_norms[c] - 2.f * dot;     // nq const per q: rank-safe
            ci[s] = c;
        } else { dv[s] = CUDART_INF_F; ci[s] = -1; }
    }

#pragma unroll 1
    for (int s = 0; s < K_NN; ++s) {
        float m = dv[0]; int idx = ci[0], key = lane * 4;
        if (dv[1] < m) { m = dv[1]; idx = ci[1]; key = lane * 4 + 1; }
        if (dv[2] < m) { m = dv[2]; idx = ci[2]; key = lane * 4 + 2; }
#pragma unroll
        for (int off = 16; off > 0; off >>= 1) {
            float om = __shfl_xor_sync(0xffffffffu, m, off);
            int   oi = __shfl_xor_sync(0xffffffffu, idx, off);
            int   ok = __shfl_xor_sync(0xffffffffu, key, off);
            if (om < m || (om == m && ok < key)) { m = om; idx = oi; key = ok; }
        }
        if ((key >> 2) == lane) dv[key & 3] = CUDART_INF_F;   // consume winner
        if (lane == 0) g_knn[q * K_NN + s] = idx;
    }
}

// ---------------------------------------------------------------------------
// Kernel 3: gather + edge-MLP + relu + max over K + pixel-shuffle (R5 version)
// ---------------------------------------------------------------------------
#define MLP_SMEM_FLOATS (32768 + 8 * 2048)

__global__ __launch_bounds__(256) void mlp_kernel(const float* __restrict__ x,
                                                  const float* __restrict__ W,
                                                  const float* __restrict__ b,
                                                  float* __restrict__ y) {
    extern __shared__ float fsm[];
    float* sW    = fsm;
    float* sfeat = fsm + 32768;

    int tid  = threadIdx.x;
    int warp = tid >> 5;
    int lane = tid & 31;

    {
        const float4* Wv = (const float4*)W;
        float4* sWv = (float4*)sW;
        for (int i = tid; i < 8192; i += 256) sWv[i] = Wv[i];
    }
    float bb[8];
#pragma unroll
    for (int k = 0; k < 8; ++k) bb[k] = b[lane * 8 + k];
    __syncthreads();

    float* f = sfeat + warp * 2048;
    const float4* f4  = (const float4*)f;
    const float4* sW4 = (const float4*)sW;

    for (int qg = blockIdx.x; qg < N_PTS / 8; qg += gridDim.x) {
        int q = qg * 8 + warp;

        float xi0 = x[(size_t)q * 64 + lane];
        float xi1 = x[(size_t)q * 64 + 32 + lane];
#pragma unroll 1
        for (int n = 0; n < 16; ++n) {
            int j = g_knn[q * 16 + n];
            float v0 = x[(size_t)j * 64 + lane];
            float v1 = x[(size_t)j * 64 + 32 + lane];
            f[n * 128 + lane]      = xi0;
            f[n * 128 + 32 + lane] = xi1;
            f[n * 128 + 64 + lane] = v0 - xi0;
            f[n * 128 + 96 + lane] = v1 - xi1;
        }
        __syncwarp();

        float vmax[8];
#pragma unroll
        for (int k = 0; k < 8; ++k) vmax[k] = 0.f;

#pragma unroll 1
        for (int ch = 0; ch < 2; ++ch) {
            float acc[8][8];
#pragma unroll
            for (int n = 0; n < 8; ++n)
#pragma unroll
                for (int k = 0; k < 8; ++k) acc[n][k] = bb[k];

#pragma unroll 1
            for (int d = 0; d < 128; d += 4) {
                float4 fv[8];
#pragma unroll
                for (int n = 0; n < 8; ++n)
                    fv[n] = f4[(ch * 8 + n) * 32 + (d >> 2)];
#pragma unroll
                for (int dd = 0; dd < 4; ++dd) {
                    float4 w0 = sW4[(d + dd) * 64 + lane * 2];
                    float4 w1 = sW4[(d + dd) * 64 + lane * 2 + 1];
#pragma unroll
                    for (int n = 0; n < 8; ++n) {
                        float fe = (dd == 0) ? fv[n].x : (dd == 1) ? fv[n].y
                                 : (dd == 2) ? fv[n].z : fv[n].w;
                        acc[n][0] = fmaf(fe, w0.x, acc[n][0]);
                        acc[n][1] = fmaf(fe, w0.y, acc[n][1]);
                        acc[n][2] = fmaf(fe, w0.z, acc[n][2]);
                        acc[n][3] = fmaf(fe, w0.w, acc[n][3]);
                        acc[n][4] = fmaf(fe, w1.x, acc[n][4]);
                        acc[n][5] = fmaf(fe, w1.y, acc[n][5]);
                        acc[n][6] = fmaf(fe, w1.z, acc[n][6]);
                        acc[n][7] = fmaf(fe, w1.w, acc[n][7]);
                    }
                }
            }
#pragma unroll
            for (int n = 0; n < 8; ++n)
#pragma unroll
                for (int k = 0; k < 8; ++k)
                    vmax[k] = fmaxf(vmax[k], fmaxf(acc[n][k], 0.f));
        }

#pragma unroll
        for (int r = 0; r < 4; ++r) {
            float2 v = make_float2(vmax[r], vmax[4 + r]);
            ((float2*)(y + (size_t)(q * 4 + r) * 64))[lane] = v;
        }
        __syncwarp();
    }
}

// ---------------------------------------------------------------------------
extern "C" void kernel_launch(void* const* d_in, const int* in_sizes, int n_in,
                              void* d_out, int out_size) {
    const float* x = (const float*)d_in[0];
    const float* W = (const float*)d_in[1];
    const float* b = (const float*)d_in[2];
    float* y = (float*)d_out;

    prep_kernel<<<N_PTS / 256, 256>>>(x);

    dim3 sgrid(N_PTS / QT, SPLIT);
    screen_kernel<<<sgrid, QT>>>();

    rerank_kernel<<<N_PTS / 8, 256>>>(x);

    cudaFuncSetAttribute(mlp_kernel,
                         cudaFuncAttributeMaxDynamicSharedMemorySize,
                         MLP_SMEM_FLOATS * sizeof(float));
    mlp_kernel<<<148, 256, MLP_SMEM_FLOATS * sizeof(float)>>>(x, W, b, y);
}

// round 11
// speedup vs baseline: 3.4746x; 1.2940x over previous
#include <cuda_runtime.h>
#include <cuda_fp16.h>
#include <math_constants.h>
#include <cstdint>

#define N_PTS 16384
#define C_DIM 64
#define K_NN 16
#define SPLIT 8
#define SEG (N_PTS / SPLIT)
#define K_SEL 20
#define K_CAND (SPLIT * K_SEL)   // 160

__device__ float g_norms[N_PTS];
__device__ __half g_xh[N_PTS * C_DIM];
__device__ int g_pi[N_PTS * K_CAND];
__device__ int g_knn[N_PTS * K_NN];

// ---------------------------------------------------------------------------
// Kernel 0: norms + fp16 copy of x
// ---------------------------------------------------------------------------
__global__ __launch_bounds__(256) void prep_kernel(const float* __restrict__ x) {
    int i = blockIdx.x * 256 + threadIdx.x;
    const float4* xv = (const float4*)(x + (size_t)i * C_DIM);
    __half2* oh = (__half2*)(g_xh + (size_t)i * C_DIM);
    float s = 0.f;
#pragma unroll
    for (int d = 0; d < 16; ++d) {
        float4 v = xv[d];
        s += v.x * v.x + v.y * v.y + v.z * v.z + v.w * v.w;
        oh[2 * d]     = __floats2half2_rn(v.x, v.y);
        oh[2 * d + 1] = __floats2half2_rn(v.z, v.w);
    }
    g_norms[i] = s;
}

// ---------------------------------------------------------------------------
// Kernel 1: fp16 screen with packed u32 keys.
// grid (128, 8) = 1024 CTAs x 128 thr; 7 CTAs/SM -> all co-resident.
// key = (fp16(d2) << 16) | candidate_id  (d2 >= 0 -> u32-monotone).
// Insert = branch-free IMNMX chain. Self handled later (occupies 1 slot).
// ---------------------------------------------------------------------------
#define QT 128
#define JT 128

__global__ __launch_bounds__(128, 7) void screen_kernel() {
    __shared__ __half sc[JT * C_DIM];   // 16 KB candidate tile
    __shared__ float sn[JT];

    int t = threadIdx.x;
    int q = blockIdx.x * QT + t;
    int s0 = blockIdx.y;

    // query as 32 half2 registers
    __half2 xq[32];
    {
        const uint4* xv = (const uint4*)(g_xh + (size_t)q * C_DIM);
#pragma unroll
        for (int d = 0; d < 8; ++d) *(uint4*)&xq[4 * d] = xv[d];
    }
    float nq = g_norms[q];

    unsigned bd[K_SEL];
#pragma unroll
    for (int s = 0; s < K_SEL; ++s) bd[s] = 0xFFFFFFFFu;

    int jbeg = s0 * SEG, jend = jbeg + SEG;
    for (int jt = jbeg; jt < jend; jt += JT) {
        __syncthreads();
        const uint4* src = (const uint4*)(g_xh + (size_t)jt * C_DIM);
        uint4* dst = (uint4*)sc;
#pragma unroll
        for (int i = 0; i < 8; ++i) dst[t + i * 128] = src[t + i * 128];
        sn[t] = g_norms[jt + t];
        __syncthreads();

#pragma unroll 1
        for (int j = 0; j < JT; ++j) {
            const uint4* cr = (const uint4*)(sc + j * C_DIM);
            __half2 a0 = __float2half2_rn(0.f);
            __half2 a1 = a0, a2 = a0, a3 = a0;
#pragma unroll
            for (int d = 0; d < 8; ++d) {
                uint4 v = cr[d];                      // 4 half2, broadcast
                const __half2* cc = (const __half2*)&v;
                a0 = __hfma2(xq[4 * d],     cc[0], a0);
                a1 = __hfma2(xq[4 * d + 1], cc[1], a1);
                a2 = __hfma2(xq[4 * d + 2], cc[2], a2);
                a3 = __hfma2(xq[4 * d + 3], cc[3], a3);
            }
            __half2 h = __hadd2(__hadd2(a0, a1), __hadd2(a2, a3));
            float dot = __low2float(h) + __high2float(h);
            float m = fmaf(-2.f, dot, nq + sn[j]);    // exact-form d2, >= ~0 always
            unsigned key = ((unsigned)__half_as_ushort(__float2half_rn(m)) << 16)
                         | (unsigned)(jt + j);
            if (key < bd[K_SEL - 1]) {
                unsigned cur = key;
#pragma unroll
                for (int s = 0; s < K_SEL; ++s) {
                    unsigned lo = min(bd[s], cur);
                    cur = max(bd[s], cur);
                    bd[s] = lo;
                }
            }
        }
    }

    int lb = q * K_CAND + s0 * K_SEL;
#pragma unroll
    for (int s = 0; s < K_SEL; ++s) g_pi[lb + s] = (int)(bd[s] & 0xFFFFu);
}

// ---------------------------------------------------------------------------
// Kernel 2: exact fp32 rerank of 160 candidates -> top-16 set (warp/query).
// Butterfly-shuffle argmin; self excluded here.
// ---------------------------------------------------------------------------
__global__ __launch_bounds__(256) void rerank_kernel(const float* __restrict__ x) {
    int w = threadIdx.x >> 5, lane = threadIdx.x & 31;
    int q = blockIdx.x * 8 + w;
    const float4* xq = (const float4*)(x + (size_t)q * C_DIM);

    float dv[5]; int ci[5];
#pragma unroll
    for (int s = 0; s < 5; ++s) {
        int i = s * 32 + lane;
        int c = g_pi[q * K_CAND + i];
        if (c != q) {
            const float4* xc = (const float4*)(x + (size_t)c * C_DIM);
            float a0 = 0.f, a1 = 0.f, a2 = 0.f, a3 = 0.f;
#pragma unroll
            for (int d = 0; d < 16; ++d) {
                float4 u = xq[d], v = xc[d];
                a0 = fmaf(u.x, v.x, a0);
                a1 = fmaf(u.y, v.y, a1);
                a2 = fmaf(u.z, v.z, a2);
                a3 = fmaf(u.w, v.w, a3);
            }
            float dot = (a0 + a1) + (a2 + a3);
            dv[s] = g_norms[c] - 2.f * dot;     // nq const per q: rank-safe
            ci[s] = c;
        } else { dv[s] = CUDART_INF_F; ci[s] = -1; }
    }

#pragma unroll 1
    for (int s = 0; s < K_NN; ++s) {
        float m = dv[0]; int idx = ci[0], key = lane;
#pragma unroll
        for (int u = 1; u < 5; ++u)
            if (dv[u] < m) { m = dv[u]; idx = ci[u]; key = u * 32 + lane; }
#pragma unroll
        for (int off = 16; off > 0; off >>= 1) {
            float om = __shfl_xor_sync(0xffffffffu, m, off);
            int   oi = __shfl_xor_sync(0xffffffffu, idx, off);
            int   ok = __shfl_xor_sync(0xffffffffu, key, off);
            if (om < m || (om == m && ok < key)) { m = om; idx = oi; key = ok; }
        }
        if ((key & 31) == lane && (key >> 5) < 5 && key >= 0) {
            // consume the winner on its owner lane
            int slot = key >> 5;
            if (slot == 0) dv[0] = CUDART_INF_F;
            else if (slot == 1) dv[1] = CUDART_INF_F;
            else if (slot == 2) dv[2] = CUDART_INF_F;
            else if (slot == 3) dv[3] = CUDART_INF_F;
            else dv[4] = CUDART_INF_F;
        }
        if (lane == 0) g_knn[q * K_NN + s] = idx;
    }
}

// ---------------------------------------------------------------------------
// Kernel 3: gather + edge-MLP + relu + max over K + pixel-shuffle (R5 version)
// ---------------------------------------------------------------------------
#define MLP_SMEM_FLOATS (32768 + 8 * 2048)

__global__ __launch_bounds__(256) void mlp_kernel(const float* __restrict__ x,
                                                  const float* __restrict__ W,
                                                  const float* __restrict__ b,
                                                  float* __restrict__ y) {
    extern __shared__ float fsm[];
    float* sW    = fsm;
    float* sfeat = fsm + 32768;

    int tid  = threadIdx.x;
    int warp = tid >> 5;
    int lane = tid & 31;

    {
        const float4* Wv = (const float4*)W;
        float4* sWv = (float4*)sW;
        for (int i = tid; i < 8192; i += 256) sWv[i] = Wv[i];
    }
    float bb[8];
#pragma unroll
    for (int k = 0; k < 8; ++k) bb[k] = b[lane * 8 + k];
    __syncthreads();

    float* f = sfeat + warp * 2048;
    const float4* f4  = (const float4*)f;
    const float4* sW4 = (const float4*)sW;

    for (int qg = blockIdx.x; qg < N_PTS / 8; qg += gridDim.x) {
        int q = qg * 8 + warp;

        float xi0 = x[(size_t)q * 64 + lane];
        float xi1 = x[(size_t)q * 64 + 32 + lane];
#pragma unroll 1
        for (int n = 0; n < 16; ++n) {
            int j = g_knn[q * 16 + n];
            float v0 = x[(size_t)j * 64 + lane];
            float v1 = x[(size_t)j * 64 + 32 + lane];
            f[n * 128 + lane]      = xi0;
            f[n * 128 + 32 + lane] = xi1;
            f[n * 128 + 64 + lane] = v0 - xi0;
            f[n * 128 + 96 + lane] = v1 - xi1;
        }
        __syncwarp();

        float vmax[8];
#pragma unroll
        for (int k = 0; k < 8; ++k) vmax[k] = 0.f;

#pragma unroll 1
        for (int ch = 0; ch < 2; ++ch) {
            float acc[8][8];
#pragma unroll
            for (int n = 0; n < 8; ++n)
#pragma unroll
                for (int k = 0; k < 8; ++k) acc[n][k] = bb[k];

#pragma unroll 1
            for (int d = 0; d < 128; d += 4) {
                float4 fv[8];
#pragma unroll
                for (int n = 0; n < 8; ++n)
                    fv[n] = f4[(ch * 8 + n) * 32 + (d >> 2)];
#pragma unroll
                for (int dd = 0; dd < 4; ++dd) {
                    float4 w0 = sW4[(d + dd) * 64 + lane * 2];
                    float4 w1 = sW4[(d + dd) * 64 + lane * 2 + 1];
#pragma unroll
                    for (int n = 0; n < 8; ++n) {
                        float fe = (dd == 0) ? fv[n].x : (dd == 1) ? fv[n].y
                                 : (dd == 2) ? fv[n].z : fv[n].w;
                        acc[n][0] = fmaf(fe, w0.x, acc[n][0]);
                        acc[n][1] = fmaf(fe, w0.y, acc[n][1]);
                        acc[n][2] = fmaf(fe, w0.z, acc[n][2]);
                        acc[n][3] = fmaf(fe, w0.w, acc[n][3]);
                        acc[n][4] = fmaf(fe, w1.x, acc[n][4]);
                        acc[n][5] = fmaf(fe, w1.y, acc[n][5]);
                        acc[n][6] = fmaf(fe, w1.z, acc[n][6]);
                        acc[n][7] = fmaf(fe, w1.w, acc[n][7]);
                    }
                }
            }
#pragma unroll
            for (int n = 0; n < 8; ++n)
#pragma unroll
                for (int k = 0; k < 8; ++k)
                    vmax[k] = fmaxf(vmax[k], fmaxf(acc[n][k], 0.f));
        }

#pragma unroll
        for (int r = 0; r < 4; ++r) {
            float2 v = make_float2(vmax[r], vmax[4 + r]);
            ((float2*)(y + (size_t)(q * 4 + r) * 64))[lane] = v;
        }
        __syncwarp();
    }
}

// ---------------------------------------------------------------------------
extern "C" void kernel_launch(void* const* d_in, const int* in_sizes, int n_in,
                              void* d_out, int out_size) {
    const float* x = (const float*)d_in[0];
    const float* W = (const float*)d_in[1];
    const float* b = (const float*)d_in[2];
    float* y = (float*)d_out;

    prep_kernel<<<N_PTS / 256, 256>>>(x);

    dim3 sgrid(N_PTS / QT, SPLIT);
    screen_kernel<<<sgrid, QT>>>();

    rerank_kernel<<<N_PTS / 8, 256>>>(x);

    cudaFuncSetAttribute(mlp_kernel,
                         cudaFuncAttributeMaxDynamicSharedMemorySize,
                         MLP_SMEM_FLOATS * sizeof(float));
    mlp_kernel<<<148, 256, MLP_SMEM_FLOATS * sizeof(float)>>>(x, W, b, y);
}

// round 12
// speedup vs baseline: 3.8253x; 1.1009x over previous
#include <cuda_runtime.h>
#include <cuda_fp16.h>
#include <math_constants.h>
#include <cstdint>

#define N_PTS 16384
#define C_DIM 64
#define K_NN 16
#define SPLIT 8
#define SEG (N_PTS / SPLIT)
#define K_SEL 20
#define K_CAND (SPLIT * K_SEL)   // 160

__device__ float g_norms[N_PTS];
__device__ __half g_xh[N_PTS * C_DIM];
__device__ int g_pi[N_PTS * K_CAND];
__device__ int g_knn[N_PTS * K_NN];

// ---------------------------------------------------------------------------
// Kernel 0: norms + fp16 copy of x
// ---------------------------------------------------------------------------
__global__ __launch_bounds__(256) void prep_kernel(const float* __restrict__ x) {
    int i = blockIdx.x * 256 + threadIdx.x;
    const float4* xv = (const float4*)(x + (size_t)i * C_DIM);
    __half2* oh = (__half2*)(g_xh + (size_t)i * C_DIM);
    float s = 0.f;
#pragma unroll
    for (int d = 0; d < 16; ++d) {
        float4 v = xv[d];
        s += v.x * v.x + v.y * v.y + v.z * v.z + v.w * v.w;
        oh[2 * d]     = __floats2half2_rn(v.x, v.y);
        oh[2 * d + 1] = __floats2half2_rn(v.z, v.w);
    }
    g_norms[i] = s;
}

// ---------------------------------------------------------------------------
// Kernel 1: fp16 screen with packed u32 keys (R10, unchanged).
// ---------------------------------------------------------------------------
#define QT 128
#define JT 128

__global__ __launch_bounds__(128, 7) void screen_kernel() {
    __shared__ __half sc[JT * C_DIM];   // 16 KB candidate tile
    __shared__ float sn[JT];

    int t = threadIdx.x;
    int q = blockIdx.x * QT + t;
    int s0 = blockIdx.y;

    __half2 xq[32];
    {
        const uint4* xv = (const uint4*)(g_xh + (size_t)q * C_DIM);
#pragma unroll
        for (int d = 0; d < 8; ++d) *(uint4*)&xq[4 * d] = xv[d];
    }
    float nq = g_norms[q];

    unsigned bd[K_SEL];
#pragma unroll
    for (int s = 0; s < K_SEL; ++s) bd[s] = 0xFFFFFFFFu;

    int jbeg = s0 * SEG, jend = jbeg + SEG;
    for (int jt = jbeg; jt < jend; jt += JT) {
        __syncthreads();
        const uint4* src = (const uint4*)(g_xh + (size_t)jt * C_DIM);
        uint4* dst = (uint4*)sc;
#pragma unroll
        for (int i = 0; i < 8; ++i) dst[t + i * 128] = src[t + i * 128];
        sn[t] = g_norms[jt + t];
        __syncthreads();

#pragma unroll 1
        for (int j = 0; j < JT; ++j) {
            const uint4* cr = (const uint4*)(sc + j * C_DIM);
            __half2 a0 = __float2half2_rn(0.f);
            __half2 a1 = a0, a2 = a0, a3 = a0;
#pragma unroll
            for (int d = 0; d < 8; ++d) {
                uint4 v = cr[d];                      // 4 half2, broadcast
                const __half2* cc = (const __half2*)&v;
                a0 = __hfma2(xq[4 * d],     cc[0], a0);
                a1 = __hfma2(xq[4 * d + 1], cc[1], a1);
                a2 = __hfma2(xq[4 * d + 2], cc[2], a2);
                a3 = __hfma2(xq[4 * d + 3], cc[3], a3);
            }
            __half2 h = __hadd2(__hadd2(a0, a1), __hadd2(a2, a3));
            float dot = __low2float(h) + __high2float(h);
            float m = fmaf(-2.f, dot, nq + sn[j]);
            unsigned key = ((unsigned)__half_as_ushort(__float2half_rn(m)) << 16)
                         | (unsigned)(jt + j);
            if (key < bd[K_SEL - 1]) {
                unsigned cur = key;
#pragma unroll
                for (int s = 0; s < K_SEL; ++s) {
                    unsigned lo = min(bd[s], cur);
                    cur = max(bd[s], cur);
                    bd[s] = lo;
                }
            }
        }
    }

    int lb = q * K_CAND + s0 * K_SEL;
#pragma unroll
    for (int s = 0; s < K_SEL; ++s) g_pi[lb + s] = (int)(bd[s] & 0xFFFFu);
}

// ---------------------------------------------------------------------------
// Kernel 2: exact fp32 rerank of 160 candidates -> top-16 set (R10, unchanged)
// ---------------------------------------------------------------------------
__global__ __launch_bounds__(256) void rerank_kernel(const float* __restrict__ x) {
    int w = threadIdx.x >> 5, lane = threadIdx.x & 31;
    int q = blockIdx.x * 8 + w;
    const float4* xq = (const float4*)(x + (size_t)q * C_DIM);

    float dv[5]; int ci[5];
#pragma unroll
    for (int s = 0; s < 5; ++s) {
        int i = s * 32 + lane;
        int c = g_pi[q * K_CAND + i];
        if (c != q) {
            const float4* xc = (const float4*)(x + (size_t)c * C_DIM);
            float a0 = 0.f, a1 = 0.f, a2 = 0.f, a3 = 0.f;
#pragma unroll
            for (int d = 0; d < 16; ++d) {
                float4 u = xq[d], v = xc[d];
                a0 = fmaf(u.x, v.x, a0);
                a1 = fmaf(u.y, v.y, a1);
                a2 = fmaf(u.z, v.z, a2);
                a3 = fmaf(u.w, v.w, a3);
            }
            float dot = (a0 + a1) + (a2 + a3);
            dv[s] = g_norms[c] - 2.f * dot;
            ci[s] = c;
        } else { dv[s] = CUDART_INF_F; ci[s] = -1; }
    }

#pragma unroll 1
    for (int s = 0; s < K_NN; ++s) {
        float m = dv[0]; int idx = ci[0], key = lane;
#pragma unroll
        for (int u = 1; u < 5; ++u)
            if (dv[u] < m) { m = dv[u]; idx = ci[u]; key = u * 32 + lane; }
#pragma unroll
        for (int off = 16; off > 0; off >>= 1) {
            float om = __shfl_xor_sync(0xffffffffu, m, off);
            int   oi = __shfl_xor_sync(0xffffffffu, idx, off);
            int   ok = __shfl_xor_sync(0xffffffffu, key, off);
            if (om < m || (om == m && ok < key)) { m = om; idx = oi; key = ok; }
        }
        if ((key & 31) == lane) {
            int slot = key >> 5;
            if (slot == 0) dv[0] = CUDART_INF_F;
            else if (slot == 1) dv[1] = CUDART_INF_F;
            else if (slot == 2) dv[2] = CUDART_INF_F;
            else if (slot == 3) dv[3] = CUDART_INF_F;
            else dv[4] = CUDART_INF_F;
        }
        if (lane == 0) g_knn[q * K_NN + s] = idx;
    }
}

// ---------------------------------------------------------------------------
// Kernel 3: factored edge-MLP.
// feat@W = x_i@W[0:64] (neighbor-invariant, once per query)
//        + (x_j - x_i)@W[64:128] (per neighbor, 64 dims only).
// Per-warp smem: f[0:64] = x_i, f[64 + n*64 ...] = x_j - x_i.
// ---------------------------------------------------------------------------
#define MLP_SMEM_FLOATS (32768 + 8 * 1088)   // W(128x256) + 8 x (64 + 16*64)

__global__ __launch_bounds__(256) void mlp_kernel(const float* __restrict__ x,
                                                  const float* __restrict__ W,
                                                  const float* __restrict__ b,
                                                  float* __restrict__ y) {
    extern __shared__ float fsm[];
    float* sW    = fsm;
    float* sfeat = fsm + 32768;

    int tid  = threadIdx.x;
    int warp = tid >> 5;
    int lane = tid & 31;

    {
        const float4* Wv = (const float4*)W;
        float4* sWv = (float4*)sW;
        for (int i = tid; i < 8192; i += 256) sWv[i] = Wv[i];
    }
    float bb[8];
#pragma unroll
    for (int k = 0; k < 8; ++k) bb[k] = b[lane * 8 + k];
    __syncthreads();

    float* f = sfeat + warp * 1088;           // [0:64]=x_i, then 16 x 64 diffs
    const float4* f4  = (const float4*)f;
    const float4* sW4 = (const float4*)sW;

    for (int qg = blockIdx.x; qg < N_PTS / 8; qg += gridDim.x) {
        int q = qg * 8 + warp;

        float xi0 = x[(size_t)q * 64 + lane];
        float xi1 = x[(size_t)q * 64 + 32 + lane];
        f[lane]      = xi0;
        f[32 + lane] = xi1;
#pragma unroll 1
        for (int n = 0; n < 16; ++n) {
            int j = g_knn[q * 16 + n];
            float v0 = x[(size_t)j * 64 + lane];
            float v1 = x[(size_t)j * 64 + 32 + lane];
            f[64 + n * 64 + lane]      = v0 - xi0;
            f[64 + n * 64 + 32 + lane] = v1 - xi1;
        }
        __syncwarp();

        // neighbor-invariant base: bb + x_i @ W[0:64]
        float base[8];
#pragma unroll
        for (int k = 0; k < 8; ++k) base[k] = bb[k];
#pragma unroll 2
        for (int d = 0; d < 64; d += 4) {
            float4 fe4 = f4[d >> 2];                         // broadcast
#pragma unroll
            for (int dd = 0; dd < 4; ++dd) {
                float4 w0 = sW4[(d + dd) * 64 + lane * 2];
                float4 w1 = sW4[(d + dd) * 64 + lane * 2 + 1];
                float fe = (dd == 0) ? fe4.x : (dd == 1) ? fe4.y
                         : (dd == 2) ? fe4.z : fe4.w;
                base[0] = fmaf(fe, w0.x, base[0]);
                base[1] = fmaf(fe, w0.y, base[1]);
                base[2] = fmaf(fe, w0.z, base[2]);
                base[3] = fmaf(fe, w0.w, base[3]);
                base[4] = fmaf(fe, w1.x, base[4]);
                base[5] = fmaf(fe, w1.y, base[5]);
                base[6] = fmaf(fe, w1.z, base[6]);
                base[7] = fmaf(fe, w1.w, base[7]);
            }
        }

        float vmax[8];
#pragma unroll
        for (int k = 0; k < 8; ++k) vmax[k] = 0.f;           // relu >= 0

#pragma unroll 1
        for (int ch = 0; ch < 2; ++ch) {                     // 8 neighbors/chunk
            float acc[8][8];
#pragma unroll
            for (int n = 0; n < 8; ++n)
#pragma unroll
                for (int k = 0; k < 8; ++k) acc[n][k] = base[k];

#pragma unroll 1
            for (int d = 0; d < 64; d += 4) {
                float4 fv[8];
#pragma unroll
                for (int n = 0; n < 8; ++n)
                    fv[n] = f4[16 + (ch * 8 + n) * 16 + (d >> 2)];   // broadcast
#pragma unroll
                for (int dd = 0; dd < 4; ++dd) {
                    float4 w0 = sW4[(64 + d + dd) * 64 + lane * 2];
                    float4 w1 = sW4[(64 + d + dd) * 64 + lane * 2 + 1];
#pragma unroll
                    for (int n = 0; n < 8; ++n) {
                        float fe = (dd == 0) ? fv[n].x : (dd == 1) ? fv[n].y
                                 : (dd == 2) ? fv[n].z : fv[n].w;
                        acc[n][0] = fmaf(fe, w0.x, acc[n][0]);
                        acc[n][1] = fmaf(fe, w0.y, acc[n][1]);
                        acc[n][2] = fmaf(fe, w0.z, acc[n][2]);
                        acc[n][3] = fmaf(fe, w0.w, acc[n][3]);
                        acc[n][4] = fmaf(fe, w1.x, acc[n][4]);
                        acc[n][5] = fmaf(fe, w1.y, acc[n][5]);
                        acc[n][6] = fmaf(fe, w1.z, acc[n][6]);
                        acc[n][7] = fmaf(fe, w1.w, acc[n][7]);
                    }
                }
            }
#pragma unroll
            for (int n = 0; n < 8; ++n)
#pragma unroll
                for (int k = 0; k < 8; ++k)
                    vmax[k] = fmaxf(vmax[k], fmaxf(acc[n][k], 0.f));
        }

        // m = lane*8+k ; c = m>>2 ; r = m&3 ; y[(q*4+r)*64 + c]
#pragma unroll
        for (int r = 0; r < 4; ++r) {
            float2 v = make_float2(vmax[r], vmax[4 + r]);
            ((float2*)(y + (size_t)(q * 4 + r) * 64))[lane] = v;
        }
        __syncwarp();
    }
}

// ---------------------------------------------------------------------------
extern "C" void kernel_launch(void* const* d_in, const int* in_sizes, int n_in,
                              void* d_out, int out_size) {
    const float* x = (const float*)d_in[0];
    const float* W = (const float*)d_in[1];
    const float* b = (const float*)d_in[2];
    float* y = (float*)d_out;

    prep_kernel<<<N_PTS / 256, 256>>>(x);

    dim3 sgrid(N_PTS / QT, SPLIT);
    screen_kernel<<<sgrid, QT>>>();

    rerank_kernel<<<N_PTS / 8, 256>>>(x);

    cudaFuncSetAttribute(mlp_kernel,
                         cudaFuncAttributeMaxDynamicSharedMemorySize,
                         MLP_SMEM_FLOATS * sizeof(float));
    mlp_kernel<<<148, 256, MLP_SMEM_FLOATS * sizeof(float)>>>(x, W, b, y);
}